// round 4
// baseline (speedup 1.0000x reference)
#include <cuda_runtime.h>
#include <stdint.h>

#define NMAX 100000
#define EMAX 1000000
#define D 64

// ---------------- scratch (device globals: no allocation allowed) ----------------
__device__ __align__(16) float g_x [NMAX * D];   // normalized input features
__device__ __align__(16) float g_x1[NMAX * D];   // layer-1 activations
__device__ __align__(16) float g_h [NMAX * D];   // per-layer linear output
__device__ float g_dinv[NMAX];
__device__ int   g_deg [NMAX];
__device__ int   g_ptr [NMAX];
__device__ int   g_cur [NMAX];
__device__ int   g_srcA[2 * EMAX]; // CSR: source node per directed edge
__device__ float g_wA  [2 * EMAX]; // CSR: edge weight dinv[u]*dinv[v]
__device__ int   g_bsums[1024];
__device__ int   g_boffs[1024];
__device__ int   g_is64;           // 1 => edge_index delivered as int64

// ---------------- edge-index dtype handling ----------------
__device__ __forceinline__ int get_idx(const void* ei, int i) {
    if (g_is64) return (int)((const long long*)ei)[i];
    return ((const int*)ei)[i];
}

// reset flag + init degrees (self loop)
__global__ void k_init(int N) {
    int i = blockIdx.x * blockDim.x + threadIdx.x;
    if (i == 0) g_is64 = 1;
    if (i < N) g_deg[i] = 1;
}

// Sample first `ns` logical entries. If int64, the high 32-bit word of every
// value (< 2^31, non-negative) is zero. Any nonzero odd word => int32 layout.
__global__ void k_detect(const int* __restrict__ w, int ns) {
    int i = blockIdx.x * blockDim.x + threadIdx.x;
    if (i < ns && w[2 * i + 1] != 0) g_is64 = 0;
}

__global__ void k_count(const void* __restrict__ ei, int twoE, int N) {
    int i = blockIdx.x * blockDim.x + threadIdx.x;
    if (i < twoE) {
        int u = get_idx(ei, i);
        if ((unsigned)u < (unsigned)N) atomicAdd(&g_deg[u], 1);
    }
}

__global__ void k_dinv(int N) {
    int i = blockIdx.x * blockDim.x + threadIdx.x;
    if (i < N) g_dinv[i] = rsqrtf((float)g_deg[i]);
}

// exclusive scan over (deg[i]-1), 1024 elems per block
__global__ void k_scan1(int N) {
    __shared__ int s[1024];
    int tid = threadIdx.x;
    int i = blockIdx.x * 1024 + tid;
    int v = (i < N) ? (g_deg[i] - 1) : 0;
    s[tid] = v;
    __syncthreads();
    for (int off = 1; off < 1024; off <<= 1) {
        int t = (tid >= off) ? s[tid - off] : 0;
        __syncthreads();
        s[tid] += t;
        __syncthreads();
    }
    if (i < N) g_ptr[i] = s[tid] - v;           // exclusive within block
    if (tid == 1023) g_bsums[blockIdx.x] = s[1023];
}

__global__ void k_scan2(int B) {
    __shared__ int s[1024];
    int tid = threadIdx.x;
    int v = (tid < B) ? g_bsums[tid] : 0;
    s[tid] = v;
    __syncthreads();
    for (int off = 1; off < 1024; off <<= 1) {
        int t = (tid >= off) ? s[tid - off] : 0;
        __syncthreads();
        s[tid] += t;
        __syncthreads();
    }
    if (tid < B) g_boffs[tid] = s[tid] - v;     // exclusive block offsets
}

__global__ void k_scan3(int N) {
    int i = blockIdx.x * blockDim.x + threadIdx.x;
    if (i < N) {
        int p = g_ptr[i] + g_boffs[i >> 10];
        g_ptr[i] = p;
        g_cur[i] = p;
    }
}

__global__ void k_place(const void* __restrict__ ei, int E, int N) {
    int e = blockIdx.x * blockDim.x + threadIdx.x;
    if (e >= E) return;
    int u = get_idx(ei, e);
    int v = get_idx(ei, E + e);
    if ((unsigned)u >= (unsigned)N || (unsigned)v >= (unsigned)N) return;
    float w = g_dinv[u] * g_dinv[v];
    int p = atomicAdd(&g_cur[v], 1);
    if ((unsigned)p < 2u * EMAX) { g_srcA[p] = u; g_wA[p] = w; }
    int q = atomicAdd(&g_cur[u], 1);
    if ((unsigned)q < 2u * EMAX) { g_srcA[q] = v; g_wA[q] = w; }
}

// ---------------- L2-normalize rows: one warp per node ----------------
__global__ void k_normalize(const float* __restrict__ emb, int N) {
    int warp = (blockIdx.x * blockDim.x + threadIdx.x) >> 5;
    int lane = threadIdx.x & 31;
    if (warp >= N) return;
    const float2* r = (const float2*)(emb + (size_t)warp * D);
    float2 v = r[lane];
    float s = v.x * v.x + v.y * v.y;
    #pragma unroll
    for (int o = 16; o; o >>= 1) s += __shfl_xor_sync(0xFFFFFFFFu, s, o);
    float nrm = sqrtf(s);
    float inv = 1.0f / fmaxf(nrm, 1e-12f);
    float2* o2 = (float2*)(g_x + (size_t)warp * D);
    o2[lane] = make_float2(v.x * inv, v.y * inv);
}

// ---------------- GEMM: h = in @ W^T ----------------
// 64-node tile per block, 256 threads; W^T and the input tile staged in smem.
__global__ void k_gemm(int insel, const float* __restrict__ W, int N) {
    __shared__ float s_in[64 * 64];
    __shared__ float s_wt[64 * 64];  // s_wt[k*64 + j] = W[j*64 + k]
    const float* __restrict__ in = insel ? g_x1 : g_x;

    int tid  = threadIdx.x;
    int base = blockIdx.x * 64;

    const float4* in4  = (const float4*)(in + (size_t)base * D);
    float4*       sin4 = (float4*)s_in;
    #pragma unroll
    for (int r = 0; r < 4; r++) {
        int idx4 = tid + 256 * r;          // 1024 float4 per tile
        int row  = idx4 >> 4;              // 16 float4 per row
        sin4[idx4] = (base + row < N) ? in4[idx4]
                                      : make_float4(0.f, 0.f, 0.f, 0.f);
    }
    #pragma unroll
    for (int r = 0; r < 16; r++) {
        int idx = tid + 256 * r;           // 4096 floats
        int j = idx & 63;
        int k = idx >> 6;
        s_wt[k * 64 + j] = W[j * 64 + k];
    }
    __syncthreads();

    int ng = tid >> 4;        // node group 0..15 (4 nodes each)
    int cg = tid & 15;        // column group 0..15 (4 cols each)
    int r0 = ng * 4;

    float4 a0 = make_float4(0.f,0.f,0.f,0.f), a1 = a0, a2 = a0, a3 = a0;
    const float4* wt4 = (const float4*)s_wt;
    #pragma unroll
    for (int k = 0; k < 64; k++) {
        float4 wv = wt4[k * 16 + cg];
        float x0 = s_in[(r0 + 0) * 64 + k];
        float x1 = s_in[(r0 + 1) * 64 + k];
        float x2 = s_in[(r0 + 2) * 64 + k];
        float x3 = s_in[(r0 + 3) * 64 + k];
        a0.x += x0*wv.x; a0.y += x0*wv.y; a0.z += x0*wv.z; a0.w += x0*wv.w;
        a1.x += x1*wv.x; a1.y += x1*wv.y; a1.z += x1*wv.z; a1.w += x1*wv.w;
        a2.x += x2*wv.x; a2.y += x2*wv.y; a2.z += x2*wv.z; a2.w += x2*wv.w;
        a3.x += x3*wv.x; a3.y += x3*wv.y; a3.z += x3*wv.z; a3.w += x3*wv.w;
    }

    float4* out4 = (float4*)(g_h + (size_t)(base + r0) * D);
    if (base + r0 + 0 < N) out4[0 * 16 + cg] = a0;
    if (base + r0 + 1 < N) out4[1 * 16 + cg] = a1;
    if (base + r0 + 2 < N) out4[2 * 16 + cg] = a2;
    if (base + r0 + 3 < N) out4[3 * 16 + cg] = a3;
}

// ---------------- fused gather + bias + leaky + output accumulation ----------------
// 16 threads per node (one float4 lane each). mode: 1 = layer1 (leaky, store
// g_x1, out = x + x1), 2 = layer2 (leaky, out += x2), 3 = layer3 (no act, out += x3).
__global__ void k_gather(const float* __restrict__ bias, float* __restrict__ out,
                         int mode, int N) {
    int node = blockIdx.x * 16 + (threadIdx.x >> 4);
    int lane = threadIdx.x & 15;
    if (node >= N) return;

    float di = g_dinv[node];
    float sw = di * di;
    float4 acc = ((const float4*)(g_h + (size_t)node * D))[lane];  // self loop
    acc.x *= sw; acc.y *= sw; acc.z *= sw; acc.w *= sw;

    int s0  = g_ptr[node];
    int cnt = g_deg[node] - 1;
    int gbase = threadIdx.x & 16;                 // 16-lane group base within warp
    unsigned gmask = 0xFFFFu << gbase;

    for (int b = 0; b < cnt; b += 16) {
        int m = cnt - b; if (m > 16) m = 16;
        int src = 0; float w = 0.f;
        if (lane < m) {
            src = g_srcA[s0 + b + lane];
            w   = g_wA  [s0 + b + lane];
        }
        #pragma unroll 4
        for (int t = 0; t < m; t++) {
            int   ss = __shfl_sync(gmask, src, gbase | t);
            float ww = __shfl_sync(gmask, w,   gbase | t);
            float4 hv = ((const float4*)(g_h + (size_t)ss * D))[lane];
            acc.x += ww * hv.x; acc.y += ww * hv.y;
            acc.z += ww * hv.z; acc.w += ww * hv.w;
        }
    }

    float4 bb = ((const float4*)bias)[lane];
    acc.x += bb.x; acc.y += bb.y; acc.z += bb.z; acc.w += bb.w;

    if (mode != 3) {  // leaky_relu, slope 0.01
        acc.x = acc.x > 0.f ? acc.x : 0.01f * acc.x;
        acc.y = acc.y > 0.f ? acc.y : 0.01f * acc.y;
        acc.z = acc.z > 0.f ? acc.z : 0.01f * acc.z;
        acc.w = acc.w > 0.f ? acc.w : 0.01f * acc.w;
    }

    size_t o = (size_t)node * 16 + lane;
    if (mode == 1) {
        ((float4*)g_x1)[o] = acc;
        float4 xv = ((const float4*)g_x)[o];
        acc.x += xv.x; acc.y += xv.y; acc.z += xv.z; acc.w += xv.w;
        ((float4*)out)[o] = acc;                    // out = x + x1
    } else {
        float4 ov = ((float4*)out)[o];
        ov.x += acc.x; ov.y += acc.y; ov.z += acc.z; ov.w += acc.w;
        ((float4*)out)[o] = ov;                     // out += x2 / x3
    }
}

// ---------------- launch ----------------
extern "C" void kernel_launch(void* const* d_in, const int* in_sizes, int n_in,
                              void* d_out, int out_size) {
    const void*  ei  = d_in[0];
    const float* emb = (const float*)d_in[1];
    const float* W1 = (const float*)d_in[2];
    const float* b1 = (const float*)d_in[3];
    const float* W2 = (const float*)d_in[4];
    const float* b2 = (const float*)d_in[5];
    const float* W3 = (const float*)d_in[6];
    const float* b3 = (const float*)d_in[7];
    float* out = (float*)d_out;

    int E = in_sizes[0] / 2;
    int N = in_sizes[1] / D;

    // graph build (once per launch; kernels only, graph-capturable)
    k_init  <<<(N + 255) / 256, 256>>>(N);
    k_detect<<<16, 256>>>((const int*)ei, 4096);   // decide int32 vs int64
    k_count <<<(2 * E + 255) / 256, 256>>>(ei, 2 * E, N);
    k_dinv  <<<(N + 255) / 256, 256>>>(N);
    int B = (N + 1023) / 1024;
    k_scan1<<<B, 1024>>>(N);
    k_scan2<<<1, 1024>>>(B);
    k_scan3<<<(N + 255) / 256, 256>>>(N);
    k_place<<<(E + 255) / 256, 256>>>(ei, E, N);

    // x = row-L2-normalized embedding
    k_normalize<<<(N + 7) / 8, 256>>>(emb, N);

    int gb = (N + 63) / 64;   // gemm blocks
    int hb = (N + 15) / 16;   // gather blocks

    // layer 1: x1 = leaky(conv(x, W1, b1)); out = x + x1
    k_gemm  <<<gb, 256>>>(0, W1, N);
    k_gather<<<hb, 256>>>(b1, out, 1, N);
    // layer 2: out += leaky(conv(x1, W2, b2))
    k_gemm  <<<gb, 256>>>(1, W2, N);
    k_gather<<<hb, 256>>>(b2, out, 2, N);
    // layer 3: out += conv(x1, W3, b3)   (no activation; input is x1)
    k_gemm  <<<gb, 256>>>(1, W3, N);
    k_gather<<<hb, 256>>>(b3, out, 3, N);
}

// round 5
// speedup vs baseline: 1.3288x; 1.3288x over previous
#include <cuda_runtime.h>
#include <stdint.h>

#define NMAX 100000
#define EMAX 1000000
#define D 64

// ---------------- scratch (device globals; allocation forbidden) ----------------
__device__ __align__(16) float g_x [NMAX * D];   // normalized input features
__device__ __align__(16) float g_x1[NMAX * D];   // layer-1 activations
__device__ __align__(16) float g_a [NMAX * D];   // aggregation result (pre-GEMM)
__device__ float g_dinv[NMAX];
__device__ int   g_deg [NMAX];
__device__ int   g_ptr [NMAX];
__device__ int   g_cur [NMAX];
__device__ int2  g_srcw[2 * EMAX]; // CSR record: (src node, weight-as-int)
__device__ int   g_bsums[1024];
__device__ int   g_boffs[1024];
__device__ int   g_is64;           // 1 => edge_index delivered as int64

// ---------------- edge-index dtype handling ----------------
__device__ __forceinline__ int get_idx(const void* ei, int i) {
    if (g_is64) return (int)((const long long*)ei)[i];
    return ((const int*)ei)[i];
}

__global__ void k_init(int N) {
    int i = blockIdx.x * blockDim.x + threadIdx.x;
    if (i == 0) g_is64 = 1;
    if (i < N) g_deg[i] = 1;   // self loop
}

// int64 values < 2^31 have zero high words; any nonzero odd word => int32 layout
__global__ void k_detect(const int* __restrict__ w, int ns) {
    int i = blockIdx.x * blockDim.x + threadIdx.x;
    if (i < ns && w[2 * i + 1] != 0) g_is64 = 0;
}

__global__ void k_count(const void* __restrict__ ei, int twoE, int N) {
    int i = blockIdx.x * blockDim.x + threadIdx.x;
    if (i < twoE) {
        int u = get_idx(ei, i);
        if ((unsigned)u < (unsigned)N) atomicAdd(&g_deg[u], 1);
    }
}

__global__ void k_dinv(int N) {
    int i = blockIdx.x * blockDim.x + threadIdx.x;
    if (i < N) g_dinv[i] = rsqrtf((float)g_deg[i]);
}

// exclusive scan over (deg[i]-1), 1024 elems per block
__global__ void k_scan1(int N) {
    __shared__ int s[1024];
    int tid = threadIdx.x;
    int i = blockIdx.x * 1024 + tid;
    int v = (i < N) ? (g_deg[i] - 1) : 0;
    s[tid] = v;
    __syncthreads();
    for (int off = 1; off < 1024; off <<= 1) {
        int t = (tid >= off) ? s[tid - off] : 0;
        __syncthreads();
        s[tid] += t;
        __syncthreads();
    }
    if (i < N) g_ptr[i] = s[tid] - v;
    if (tid == 1023) g_bsums[blockIdx.x] = s[1023];
}

__global__ void k_scan2(int B) {
    __shared__ int s[1024];
    int tid = threadIdx.x;
    int v = (tid < B) ? g_bsums[tid] : 0;
    s[tid] = v;
    __syncthreads();
    for (int off = 1; off < 1024; off <<= 1) {
        int t = (tid >= off) ? s[tid - off] : 0;
        __syncthreads();
        s[tid] += t;
        __syncthreads();
    }
    if (tid < B) g_boffs[tid] = s[tid] - v;
}

__global__ void k_scan3(int N) {
    int i = blockIdx.x * blockDim.x + threadIdx.x;
    if (i < N) {
        int p = g_ptr[i] + g_boffs[i >> 10];
        g_ptr[i] = p;
        g_cur[i] = p;
    }
}

__global__ void k_place(const void* __restrict__ ei, int E, int N) {
    int e = blockIdx.x * blockDim.x + threadIdx.x;
    if (e >= E) return;
    int u = get_idx(ei, e);
    int v = get_idx(ei, E + e);
    if ((unsigned)u >= (unsigned)N || (unsigned)v >= (unsigned)N) return;
    int wi = __float_as_int(g_dinv[u] * g_dinv[v]);
    int p = atomicAdd(&g_cur[v], 1);
    if ((unsigned)p < 2u * EMAX) g_srcw[p] = make_int2(u, wi);
    int q = atomicAdd(&g_cur[u], 1);
    if ((unsigned)q < 2u * EMAX) g_srcw[q] = make_int2(v, wi);
}

// ---------------- L2-normalize rows: one warp per node ----------------
__global__ void k_normalize(const float* __restrict__ emb, int N) {
    int warp = (blockIdx.x * blockDim.x + threadIdx.x) >> 5;
    int lane = threadIdx.x & 31;
    if (warp >= N) return;
    const float2* r = (const float2*)(emb + (size_t)warp * D);
    float2 v = r[lane];
    float s = v.x * v.x + v.y * v.y;
    #pragma unroll
    for (int o = 16; o; o >>= 1) s += __shfl_xor_sync(0xFFFFFFFFu, s, o);
    float inv = 1.0f / fmaxf(sqrtf(s), 1e-12f);
    float2* o2 = (float2*)(g_x + (size_t)warp * D);
    o2[lane] = make_float2(v.x * inv, v.y * inv);
}

// ---------------- aggregation: a[v] = dinv[v]^2 * in[v] + sum_u w(u,v) in[u] ----------------
// 16 threads per node; edge records streamed coalesced then shfl-broadcast.
__global__ void k_gather(int insel, int N) {
    const float* __restrict__ in = insel ? g_x1 : g_x;
    int node = blockIdx.x * 16 + (threadIdx.x >> 4);
    int lane = threadIdx.x & 15;
    if (node >= N) return;

    float di = g_dinv[node];
    float sw = di * di;
    float4 acc = ((const float4*)(in + (size_t)node * D))[lane];
    acc.x *= sw; acc.y *= sw; acc.z *= sw; acc.w *= sw;

    int s0  = g_ptr[node];
    int cnt = g_deg[node] - 1;
    int gbase = threadIdx.x & 16;
    unsigned gmask = 0xFFFFu << gbase;

    for (int b = 0; b < cnt; b += 16) {
        int m = cnt - b; if (m > 16) m = 16;
        int2 rec = make_int2(0, 0);
        if (lane < m) rec = g_srcw[s0 + b + lane];
        #pragma unroll 4
        for (int t = 0; t < m; t++) {
            int   ss = __shfl_sync(gmask, rec.x, gbase | t);
            float ww = __int_as_float(__shfl_sync(gmask, rec.y, gbase | t));
            float4 hv = ((const float4*)(in + (size_t)ss * D))[lane];
            acc.x += ww * hv.x; acc.y += ww * hv.y;
            acc.z += ww * hv.z; acc.w += ww * hv.w;
        }
    }
    ((float4*)(g_a + (size_t)node * D))[lane] = acc;
}

// ---------------- GEMM 1: x1 = leaky(g_a @ W1^T + b1) ----------------
__global__ void k_gemm1(const float* __restrict__ W, const float* __restrict__ b, int N) {
    __shared__ float s_in[64 * 64];
    __shared__ float s_wt[64 * 64];  // s_wt[k*64 + j] = W[j*64 + k]

    int tid  = threadIdx.x;
    int base = blockIdx.x * 64;

    const float4* in4  = (const float4*)(g_a + (size_t)base * D);
    float4*       sin4 = (float4*)s_in;
    #pragma unroll
    for (int r = 0; r < 4; r++) {
        int idx4 = tid + 256 * r;
        int row  = idx4 >> 4;
        sin4[idx4] = (base + row < N) ? in4[idx4] : make_float4(0.f,0.f,0.f,0.f);
    }
    #pragma unroll
    for (int r = 0; r < 16; r++) {
        int idx = tid + 256 * r;
        s_wt[(idx >> 6) * 64 + (idx & 63)] = W[(idx & 63) * 64 + (idx >> 6)];
    }
    __syncthreads();

    int ng = tid >> 4, cg = tid & 15;
    int r0 = ng * 4;
    float4 a0 = make_float4(0.f,0.f,0.f,0.f), a1 = a0, a2 = a0, a3 = a0;
    const float4* wt4 = (const float4*)s_wt;
    #pragma unroll
    for (int k = 0; k < 64; k++) {
        float4 wv = wt4[k * 16 + cg];
        float x0 = s_in[(r0+0)*64+k], x1 = s_in[(r0+1)*64+k];
        float x2 = s_in[(r0+2)*64+k], x3 = s_in[(r0+3)*64+k];
        a0.x += x0*wv.x; a0.y += x0*wv.y; a0.z += x0*wv.z; a0.w += x0*wv.w;
        a1.x += x1*wv.x; a1.y += x1*wv.y; a1.z += x1*wv.z; a1.w += x1*wv.w;
        a2.x += x2*wv.x; a2.y += x2*wv.y; a2.z += x2*wv.z; a2.w += x2*wv.w;
        a3.x += x3*wv.x; a3.y += x3*wv.y; a3.z += x3*wv.z; a3.w += x3*wv.w;
    }

    float4 bb = ((const float4*)b)[cg];
    #define EPI1(v) { v.x += bb.x; v.y += bb.y; v.z += bb.z; v.w += bb.w; \
        v.x = v.x > 0.f ? v.x : 0.01f*v.x; v.y = v.y > 0.f ? v.y : 0.01f*v.y; \
        v.z = v.z > 0.f ? v.z : 0.01f*v.z; v.w = v.w > 0.f ? v.w : 0.01f*v.w; }
    EPI1(a0); EPI1(a1); EPI1(a2); EPI1(a3);

    float4* out4 = (float4*)(g_x1 + (size_t)(base + r0) * D);
    if (base + r0 + 0 < N) out4[0*16+cg] = a0;
    if (base + r0 + 1 < N) out4[1*16+cg] = a1;
    if (base + r0 + 2 < N) out4[2*16+cg] = a2;
    if (base + r0 + 3 < N) out4[3*16+cg] = a3;
}

// ---- GEMM 2+3 fused: out = x + x1 + leaky(a@W2^T + b2) + (a@W3^T + b3) ----
__global__ void k_gemm23(const float* __restrict__ W2, const float* __restrict__ b2,
                         const float* __restrict__ W3, const float* __restrict__ b3,
                         float* __restrict__ out, int N) {
    __shared__ float s_in[64 * 64];
    __shared__ float s_w2[64 * 64];
    __shared__ float s_w3[64 * 64];

    int tid  = threadIdx.x;
    int base = blockIdx.x * 64;

    const float4* in4  = (const float4*)(g_a + (size_t)base * D);
    float4*       sin4 = (float4*)s_in;
    #pragma unroll
    for (int r = 0; r < 4; r++) {
        int idx4 = tid + 256 * r;
        int row  = idx4 >> 4;
        sin4[idx4] = (base + row < N) ? in4[idx4] : make_float4(0.f,0.f,0.f,0.f);
    }
    #pragma unroll
    for (int r = 0; r < 16; r++) {
        int idx = tid + 256 * r;
        int j = idx & 63, k = idx >> 6;
        s_w2[k * 64 + j] = W2[j * 64 + k];
        s_w3[k * 64 + j] = W3[j * 64 + k];
    }
    __syncthreads();

    int ng = tid >> 4, cg = tid & 15;
    int r0 = ng * 4;
    float4 p0 = make_float4(0.f,0.f,0.f,0.f), p1 = p0, p2 = p0, p3 = p0; // W2 accum
    float4 q0 = p0, q1 = p0, q2 = p0, q3 = p0;                           // W3 accum
    const float4* w24 = (const float4*)s_w2;
    const float4* w34 = (const float4*)s_w3;
    #pragma unroll
    for (int k = 0; k < 64; k++) {
        float4 u = w24[k * 16 + cg];
        float4 v = w34[k * 16 + cg];
        float x0 = s_in[(r0+0)*64+k], x1 = s_in[(r0+1)*64+k];
        float x2 = s_in[(r0+2)*64+k], x3 = s_in[(r0+3)*64+k];
        p0.x += x0*u.x; p0.y += x0*u.y; p0.z += x0*u.z; p0.w += x0*u.w;
        p1.x += x1*u.x; p1.y += x1*u.y; p1.z += x1*u.z; p1.w += x1*u.w;
        p2.x += x2*u.x; p2.y += x2*u.y; p2.z += x2*u.z; p2.w += x2*u.w;
        p3.x += x3*u.x; p3.y += x3*u.y; p3.z += x3*u.z; p3.w += x3*u.w;
        q0.x += x0*v.x; q0.y += x0*v.y; q0.z += x0*v.z; q0.w += x0*v.w;
        q1.x += x1*v.x; q1.y += x1*v.y; q1.z += x1*v.z; q1.w += x1*v.w;
        q2.x += x2*v.x; q2.y += x2*v.y; q2.z += x2*v.z; q2.w += x2*v.w;
        q3.x += x3*v.x; q3.y += x3*v.y; q3.z += x3*v.z; q3.w += x3*v.w;
    }

    float4 bb2 = ((const float4*)b2)[cg];
    float4 bb3 = ((const float4*)b3)[cg];

    #pragma unroll
    for (int r = 0; r < 4; r++) {
        int row = base + r0 + r;
        if (row >= N) break;
        float4 p = (r==0)?p0:(r==1)?p1:(r==2)?p2:p3;
        float4 q = (r==0)?q0:(r==1)?q1:(r==2)?q2:q3;
        // x2 = leaky(p + b2)
        p.x += bb2.x; p.y += bb2.y; p.z += bb2.z; p.w += bb2.w;
        p.x = p.x > 0.f ? p.x : 0.01f*p.x; p.y = p.y > 0.f ? p.y : 0.01f*p.y;
        p.z = p.z > 0.f ? p.z : 0.01f*p.z; p.w = p.w > 0.f ? p.w : 0.01f*p.w;
        // x3 = q + b3
        q.x += bb3.x; q.y += bb3.y; q.z += bb3.z; q.w += bb3.w;
        size_t o = (size_t)row * 16 + cg;
        float4 xv  = ((const float4*)g_x )[o];
        float4 x1v = ((const float4*)g_x1)[o];
        float4 res;
        res.x = xv.x + x1v.x + p.x + q.x;
        res.y = xv.y + x1v.y + p.y + q.y;
        res.z = xv.z + x1v.z + p.z + q.z;
        res.w = xv.w + x1v.w + p.w + q.w;
        ((float4*)out)[o] = res;
    }
}

// ---------------- launch ----------------
extern "C" void kernel_launch(void* const* d_in, const int* in_sizes, int n_in,
                              void* d_out, int out_size) {
    const void*  ei  = d_in[0];
    const float* emb = (const float*)d_in[1];
    const float* W1 = (const float*)d_in[2];
    const float* b1 = (const float*)d_in[3];
    const float* W2 = (const float*)d_in[4];
    const float* b2 = (const float*)d_in[5];
    const float* W3 = (const float*)d_in[6];
    const float* b3 = (const float*)d_in[7];
    float* out = (float*)d_out;

    int E = in_sizes[0] / 2;
    int N = in_sizes[1] / D;

    // graph build
    k_init  <<<(N + 255) / 256, 256>>>(N);
    k_detect<<<16, 256>>>((const int*)ei, 4096);
    k_count <<<(2 * E + 255) / 256, 256>>>(ei, 2 * E, N);
    k_dinv  <<<(N + 255) / 256, 256>>>(N);
    int B = (N + 1023) / 1024;
    k_scan1<<<B, 1024>>>(N);
    k_scan2<<<1, 1024>>>(B);
    k_scan3<<<(N + 255) / 256, 256>>>(N);
    k_place<<<(E + 255) / 256, 256>>>(ei, E, N);

    k_normalize<<<(N + 7) / 8, 256>>>(emb, N);

    int gb = (N + 63) / 64;   // gemm blocks
    int hb = (N + 15) / 16;   // gather blocks

    // a = Agg(x);  x1 = leaky(a W1^T + b1)
    k_gather<<<hb, 256>>>(0, N);
    k_gemm1 <<<gb, 256>>>(W1, b1, N);
    // a = Agg(x1); out = x + x1 + leaky(a W2^T + b2) + (a W3^T + b3)
    k_gather<<<hb, 256>>>(1, N);
    k_gemm23<<<gb, 256>>>(W2, b2, W3, b3, out, N);
}

// round 7
// speedup vs baseline: 1.3379x; 1.0069x over previous
#include <cuda_runtime.h>
#include <cuda_bf16.h>
#include <stdint.h>

#define NMAX 100000
#define EMAX 1000000
#define D 64

// ---------------- scratch (device globals; keep total small: ~56 MB) ----------------
__device__ __align__(16) float         g_a[NMAX * D];  // aggregation output (fp32)
__device__ __align__(16) __nv_bfloat16 g_b[NMAX * D];  // bf16 features: x, then x1
__device__ float g_dinv[NMAX];
__device__ int   g_deg [NMAX];
__device__ int   g_ptr [NMAX];
__device__ int   g_cur [NMAX];
__device__ int2  g_srcw[2 * EMAX]; // CSR record: (src node, weight-as-int)
__device__ int   g_bsums[1024];
__device__ int   g_boffs[1024];
// Static init = 1 (int64 assumed). k_initdet only ever clears it (idempotent:
// input dtype never changes across replays). Deterministic.
__device__ int   g_is64 = 1;

__device__ __forceinline__ int get_idx(const void* ei, int i) {
    if (g_is64) return (int)((const long long*)ei)[i];
    return ((const int*)ei)[i];
}

// init degrees (self loop) + dtype detection
__global__ void k_initdet(const int* __restrict__ w, int ns, int N) {
    int i = blockIdx.x * blockDim.x + threadIdx.x;
    if (i < N) g_deg[i] = 1;
    // int64 values < 2^31 have zero high words; any nonzero odd word => int32
    if (i < ns && w[2 * i + 1] != 0) g_is64 = 0;
}

__global__ void k_count(const void* __restrict__ ei, int twoE, int N) {
    int i = blockIdx.x * blockDim.x + threadIdx.x;
    if (i < twoE) {
        int u = get_idx(ei, i);
        if ((unsigned)u < (unsigned)N) atomicAdd(&g_deg[u], 1);
    }
}

// exclusive scan over (deg[i]-1) + dinv, 1024 elems per block
__global__ void k_scan1(int N) {
    __shared__ int s[1024];
    int tid = threadIdx.x;
    int i = blockIdx.x * 1024 + tid;
    int v = 0;
    if (i < N) {
        int d = g_deg[i];
        g_dinv[i] = rsqrtf((float)d);
        v = d - 1;
    }
    s[tid] = v;
    __syncthreads();
    for (int off = 1; off < 1024; off <<= 1) {
        int t = (tid >= off) ? s[tid - off] : 0;
        __syncthreads();
        s[tid] += t;
        __syncthreads();
    }
    if (i < N) g_ptr[i] = s[tid] - v;
    if (tid == 1023) g_bsums[blockIdx.x] = s[1023];
}

__global__ void k_scan2(int B) {
    __shared__ int s[1024];
    int tid = threadIdx.x;
    int v = (tid < B) ? g_bsums[tid] : 0;
    s[tid] = v;
    __syncthreads();
    for (int off = 1; off < 1024; off <<= 1) {
        int t = (tid >= off) ? s[tid - off] : 0;
        __syncthreads();
        s[tid] += t;
        __syncthreads();
    }
    if (tid < B) g_boffs[tid] = s[tid] - v;
}

__global__ void k_scan3(int N) {
    int i = blockIdx.x * blockDim.x + threadIdx.x;
    if (i < N) {
        int p = g_ptr[i] + g_boffs[i >> 10];
        g_ptr[i] = p;
        g_cur[i] = p;
    }
}

__global__ void k_place(const void* __restrict__ ei, int E, int N) {
    int e = blockIdx.x * blockDim.x + threadIdx.x;
    if (e >= E) return;
    int u = get_idx(ei, e);
    int v = get_idx(ei, E + e);
    if ((unsigned)u >= (unsigned)N || (unsigned)v >= (unsigned)N) return;
    int wi = __float_as_int(g_dinv[u] * g_dinv[v]);
    int p = atomicAdd(&g_cur[v], 1);
    if ((unsigned)p < 2u * EMAX) g_srcw[p] = make_int2(u, wi);
    int q = atomicAdd(&g_cur[u], 1);
    if ((unsigned)q < 2u * EMAX) g_srcw[q] = make_int2(v, wi);
}

// ---- L2-normalize rows: one warp per node; writes out=x (fp32) + g_b (bf16) ----
__global__ void k_normalize(const float* __restrict__ emb, float* __restrict__ out, int N) {
    int warp = (blockIdx.x * blockDim.x + threadIdx.x) >> 5;
    int lane = threadIdx.x & 31;
    if (warp >= N) return;
    const float2* r = (const float2*)(emb + (size_t)warp * D);
    float2 v = r[lane];
    float s = v.x * v.x + v.y * v.y;
    #pragma unroll
    for (int o = 16; o; o >>= 1) s += __shfl_xor_sync(0xFFFFFFFFu, s, o);
    float inv = 1.0f / fmaxf(sqrtf(s), 1e-12f);
    float2 xv = make_float2(v.x * inv, v.y * inv);
    ((float2*)(out + (size_t)warp * D))[lane] = xv;
    ((__nv_bfloat162*)(g_b + (size_t)warp * D))[lane] = __float22bfloat162_rn(xv);
}

// ---- aggregation: a[v] = dinv[v]^2*b[v] + sum_u w(u,v)*b[u]; bf16 in, fp32 acc ----
// 8 lanes per node (16B = 8 bf16 each).
__global__ void k_gather(int N) {
    const __nv_bfloat16* __restrict__ in = g_b;
    int node = blockIdx.x * 32 + (threadIdx.x >> 3);
    int lane = threadIdx.x & 7;
    if (node >= N) return;

    float di = g_dinv[node];
    float sw = di * di;

    float acc[8];
    {
        float4 rv = ((const float4*)(in + (size_t)node * D))[lane];
        __nv_bfloat162* b = (__nv_bfloat162*)&rv;
        #pragma unroll
        for (int i = 0; i < 4; i++) {
            float2 f = __bfloat1622float2(b[i]);
            acc[2*i]   = sw * f.x;
            acc[2*i+1] = sw * f.y;
        }
    }

    int s0  = g_ptr[node];
    int cnt = g_deg[node] - 1;
    int gbase = threadIdx.x & 24;
    unsigned gmask = 0xFFu << gbase;

    for (int b0 = 0; b0 < cnt; b0 += 8) {
        int m = cnt - b0; if (m > 8) m = 8;
        int2 rec = make_int2(0, 0);
        if (lane < m) rec = g_srcw[s0 + b0 + lane];
        #pragma unroll 4
        for (int t = 0; t < m; t++) {
            int   ss = __shfl_sync(gmask, rec.x, gbase + t);
            float ww = __int_as_float(__shfl_sync(gmask, rec.y, gbase + t));
            float4 hv = ((const float4*)(in + (size_t)ss * D))[lane];
            __nv_bfloat162* hb = (__nv_bfloat162*)&hv;
            #pragma unroll
            for (int i = 0; i < 4; i++) {
                float2 f = __bfloat1622float2(hb[i]);
                acc[2*i]   += ww * f.x;
                acc[2*i+1] += ww * f.y;
            }
        }
    }

    float4* o = (float4*)(g_a + (size_t)node * D + lane * 8);
    o[0] = make_float4(acc[0], acc[1], acc[2], acc[3]);
    o[1] = make_float4(acc[4], acc[5], acc[6], acc[7]);
}

// ---- GEMM 1: x1 = leaky(a W1^T + b1); out += x1 (fp32 RMW); g_b = bf16(x1) ----
__global__ void k_gemm1(const float* __restrict__ W, const float* __restrict__ b,
                        float* __restrict__ out, int N) {
    __shared__ float s_in[64 * 64];
    __shared__ float s_wt[64 * 64];  // s_wt[k*64 + j] = W[j*64 + k]

    int tid  = threadIdx.x;
    int base = blockIdx.x * 64;

    const float4* in4  = (const float4*)(g_a + (size_t)base * D);
    float4*       sin4 = (float4*)s_in;
    #pragma unroll
    for (int r = 0; r < 4; r++) {
        int idx4 = tid + 256 * r;
        int row  = idx4 >> 4;
        sin4[idx4] = (base + row < N) ? in4[idx4] : make_float4(0.f,0.f,0.f,0.f);
    }
    #pragma unroll
    for (int r = 0; r < 16; r++) {
        int idx = tid + 256 * r;
        s_wt[(idx >> 6) * 64 + (idx & 63)] = W[(idx & 63) * 64 + (idx >> 6)];
    }
    __syncthreads();

    int ng = tid >> 4, cg = tid & 15;
    int r0 = ng * 4;
    float4 a0 = make_float4(0.f,0.f,0.f,0.f), a1 = a0, a2 = a0, a3 = a0;
    const float4* wt4 = (const float4*)s_wt;
    #pragma unroll
    for (int k = 0; k < 64; k++) {
        float4 wv = wt4[k * 16 + cg];
        float x0 = s_in[(r0+0)*64+k], x1 = s_in[(r0+1)*64+k];
        float x2 = s_in[(r0+2)*64+k], x3 = s_in[(r0+3)*64+k];
        a0.x += x0*wv.x; a0.y += x0*wv.y; a0.z += x0*wv.z; a0.w += x0*wv.w;
        a1.x += x1*wv.x; a1.y += x1*wv.y; a1.z += x1*wv.z; a1.w += x1*wv.w;
        a2.x += x2*wv.x; a2.y += x2*wv.y; a2.z += x2*wv.z; a2.w += x2*wv.w;
        a3.x += x3*wv.x; a3.y += x3*wv.y; a3.z += x3*wv.z; a3.w += x3*wv.w;
    }

    float4 bb = ((const float4*)b)[cg];
    #pragma unroll
    for (int r = 0; r < 4; r++) {
        int row = base + r0 + r;
        if (row >= N) break;
        float4 v = (r==0)?a0:(r==1)?a1:(r==2)?a2:a3;
        v.x += bb.x; v.y += bb.y; v.z += bb.z; v.w += bb.w;
        v.x = v.x > 0.f ? v.x : 0.01f*v.x; v.y = v.y > 0.f ? v.y : 0.01f*v.y;
        v.z = v.z > 0.f ? v.z : 0.01f*v.z; v.w = v.w > 0.f ? v.w : 0.01f*v.w;
        // bf16 mirror for next gather
        __nv_bfloat162* bo = (__nv_bfloat162*)(g_b + (size_t)row * D + cg * 4);
        bo[0] = __floats2bfloat162_rn(v.x, v.y);
        bo[1] = __floats2bfloat162_rn(v.z, v.w);
        // out += x1  (out currently holds x)
        size_t o = (size_t)row * 16 + cg;
        float4 ov = ((const float4*)out)[o];
        ov.x += v.x; ov.y += v.y; ov.z += v.z; ov.w += v.w;
        ((float4*)out)[o] = ov;
    }
}

// ---- GEMM 2+3 fused: out += leaky(a W2^T + b2) + (a W3^T + b3) ----
__global__ void k_gemm23(const float* __restrict__ W2, const float* __restrict__ b2,
                         const float* __restrict__ W3, const float* __restrict__ b3,
                         float* __restrict__ out, int N) {
    __shared__ float s_in[64 * 64];
    __shared__ float s_w2[64 * 64];
    __shared__ float s_w3[64 * 64];

    int tid  = threadIdx.x;
    int base = blockIdx.x * 64;

    const float4* in4  = (const float4*)(g_a + (size_t)base * D);
    float4*       sin4 = (float4*)s_in;
    #pragma unroll
    for (int r = 0; r < 4; r++) {
        int idx4 = tid + 256 * r;
        int row  = idx4 >> 4;
        sin4[idx4] = (base + row < N) ? in4[idx4] : make_float4(0.f,0.f,0.f,0.f);
    }
    #pragma unroll
    for (int r = 0; r < 16; r++) {
        int idx = tid + 256 * r;
        int j = idx & 63, k = idx >> 6;
        s_w2[k * 64 + j] = W2[j * 64 + k];
        s_w3[k * 64 + j] = W3[j * 64 + k];
    }
    __syncthreads();

    int ng = tid >> 4, cg = tid & 15;
    int r0 = ng * 4;
    float4 p0 = make_float4(0.f,0.f,0.f,0.f), p1 = p0, p2 = p0, p3 = p0;
    float4 q0 = p0, q1 = p0, q2 = p0, q3 = p0;
    const float4* w24 = (const float4*)s_w2;
    const float4* w34 = (const float4*)s_w3;
    #pragma unroll
    for (int k = 0; k < 64; k++) {
        float4 u = w24[k * 16 + cg];
        float4 v = w34[k * 16 + cg];
        float x0 = s_in[(r0+0)*64+k], x1 = s_in[(r0+1)*64+k];
        float x2 = s_in[(r0+2)*64+k], x3 = s_in[(r0+3)*64+k];
        p0.x += x0*u.x; p0.y += x0*u.y; p0.z += x0*u.z; p0.w += x0*u.w;
        p1.x += x1*u.x; p1.y += x1*u.y; p1.z += x1*u.z; p1.w += x1*u.w;
        p2.x += x2*u.x; p2.y += x2*u.y; p2.z += x2*u.z; p2.w += x2*u.w;
        p3.x += x3*u.x; p3.y += x3*u.y; p3.z += x3*u.z; p3.w += x3*u.w;
        q0.x += x0*v.x; q0.y += x0*v.y; q0.z += x0*v.z; q0.w += x0*v.w;
        q1.x += x1*v.x; q1.y += x1*v.y; q1.z += x1*v.z; q1.w += x1*v.w;
        q2.x += x2*v.x; q2.y += x2*v.y; q2.z += x2*v.z; q2.w += x2*v.w;
        q3.x += x3*v.x; q3.y += x3*v.y; q3.z += x3*v.z; q3.w += x3*v.w;
    }

    float4 bb2 = ((const float4*)b2)[cg];
    float4 bb3 = ((const float4*)b3)[cg];

    #pragma unroll
    for (int r = 0; r < 4; r++) {
        int row = base + r0 + r;
        if (row >= N) break;
        float4 p = (r==0)?p0:(r==1)?p1:(r==2)?p2:p3;
        float4 q = (r==0)?q0:(r==1)?q1:(r==2)?q2:q3;
        p.x += bb2.x; p.y += bb2.y; p.z += bb2.z; p.w += bb2.w;
        p.x = p.x > 0.f ? p.x : 0.01f*p.x; p.y = p.y > 0.f ? p.y : 0.01f*p.y;
        p.z = p.z > 0.f ? p.z : 0.01f*p.z; p.w = p.w > 0.f ? p.w : 0.01f*p.w;
        q.x += bb3.x; q.y += bb3.y; q.z += bb3.z; q.w += bb3.w;
        size_t o = (size_t)row * 16 + cg;
        float4 ov = ((const float4*)out)[o];   // holds x + x1
        ov.x += p.x + q.x;
        ov.y += p.y + q.y;
        ov.z += p.z + q.z;
        ov.w += p.w + q.w;
        ((float4*)out)[o] = ov;
    }
}

// ---------------- launch ----------------
extern "C" void kernel_launch(void* const* d_in, const int* in_sizes, int n_in,
                              void* d_out, int out_size) {
    const void*  ei  = d_in[0];
    const float* emb = (const float*)d_in[1];
    const float* W1 = (const float*)d_in[2];
    const float* b1 = (const float*)d_in[3];
    const float* W2 = (const float*)d_in[4];
    const float* b2 = (const float*)d_in[5];
    const float* W3 = (const float*)d_in[6];
    const float* b3 = (const float*)d_in[7];
    float* out = (float*)d_out;

    int E = in_sizes[0] / 2;
    int N = in_sizes[1] / D;

    // graph build
    int initsz = (N > 4096) ? N : 4096;
    k_initdet<<<(initsz + 255) / 256, 256>>>((const int*)ei, 4096, N);
    k_count  <<<(2 * E + 255) / 256, 256>>>(ei, 2 * E, N);
    int B = (N + 1023) / 1024;
    k_scan1<<<B, 1024>>>(N);
    k_scan2<<<1, 1024>>>(B);
    k_scan3<<<(N + 255) / 256, 256>>>(N);
    k_place<<<(E + 255) / 256, 256>>>(ei, E, N);

    // out = x; g_b = bf16(x)
    k_normalize<<<(N + 7) / 8, 256>>>(emb, out, N);

    int gb = (N + 63) / 64;   // gemm blocks
    int hb = (N + 31) / 32;   // gather blocks (32 nodes / 256-thread block)

    // a = Agg(x);  x1 = leaky(a W1^T + b1); out += x1; g_b = bf16(x1)
    k_gather<<<hb, 256>>>(N);
    k_gemm1 <<<gb, 256>>>(W1, b1, out, N);
    // a = Agg(x1); out += leaky(a W2^T + b2) + (a W3^T + b3)
    k_gather<<<hb, 256>>>(N);
    k_gemm23<<<gb, 256>>>(W2, b2, W3, b3, out, N);
}

// round 8
// speedup vs baseline: 1.4369x; 1.0739x over previous
#include <cuda_runtime.h>
#include <cuda_bf16.h>
#include <stdint.h>

#define NMAX 100000
#define EMAX 1000000
#define D 64
#define NSCANMAX 128   // >= ceil(NMAX/1024)

typedef unsigned long long u64;

// ---------------- scratch (device globals; ~56 MB total) ----------------
__device__ __align__(16) float         g_a[NMAX * D];  // aggregation output (fp32)
__device__ __align__(16) __nv_bfloat16 g_b[NMAX * D];  // bf16 features: x, then x1
__device__ float g_dinv[NMAX];
__device__ int   g_deg [NMAX];
__device__ int   g_ptr [NMAX];
__device__ int   g_cur [NMAX];
__device__ int2  g_srcw[2 * EMAX];    // CSR record: (src node, weight-as-int)
__device__ int   g_scanstat[NSCANMAX];
__device__ int   g_ticket;
// Static init = 1 (int64 assumed). Only ever cleared (idempotent across replays).
__device__ int   g_is64 = 1;

// ---------------- f32x2 packed-FMA helpers ----------------
__device__ __forceinline__ u64 pk2(float a, float b) {
    u64 r; asm("mov.b64 %0, {%1, %2};" : "=l"(r) : "f"(a), "f"(b)); return r;
}
__device__ __forceinline__ u64 fma2(u64 a, u64 b, u64 c) {
    u64 d; asm("fma.rn.f32x2 %0, %1, %2, %3;" : "=l"(d) : "l"(a), "l"(b), "l"(c)); return d;
}
__device__ __forceinline__ float2 up2(u64 a) {
    float2 f; asm("mov.b64 {%0, %1}, %2;" : "=f"(f.x), "=f"(f.y) : "l"(a)); return f;
}

__device__ __forceinline__ int get_idx(const void* ei, int i) {
    if (g_is64) return (int)((const long long*)ei)[i];
    return ((const int*)ei)[i];
}

// ---- prep: L2-normalize (warp/node) + deg init + dtype detect + scan-state reset ----
__global__ void k_prep(const float* __restrict__ emb, const int* __restrict__ w32,
                       float* __restrict__ out, int N) {
    int gtid = blockIdx.x * blockDim.x + threadIdx.x;
    int warp = gtid >> 5, lane = gtid & 31;
    if (warp < N) {
        float2 v = ((const float2*)(emb + (size_t)warp * D))[lane];
        float s = v.x * v.x + v.y * v.y;
        #pragma unroll
        for (int o = 16; o; o >>= 1) s += __shfl_xor_sync(0xFFFFFFFFu, s, o);
        float inv = 1.0f / fmaxf(sqrtf(s), 1e-12f);
        float2 xv = make_float2(v.x * inv, v.y * inv);
        ((float2*)(out + (size_t)warp * D))[lane] = xv;
        ((__nv_bfloat162*)(g_b + (size_t)warp * D))[lane] = __float22bfloat162_rn(xv);
    }
    if (gtid < N) g_deg[gtid] = 1;                       // self loop
    if (gtid < 4096 && w32[2 * gtid + 1] != 0) g_is64 = 0;
    if (gtid < NSCANMAX) g_scanstat[gtid] = 0;
    if (gtid == 0) g_ticket = 0;
}

__global__ void k_count(const void* __restrict__ ei, int twoE, int N) {
    int i = blockIdx.x * blockDim.x + threadIdx.x;
    if (i < twoE) {
        int u = get_idx(ei, i);
        if ((unsigned)u < (unsigned)N) atomicAdd(&g_deg[u], 1);
    }
}

// ---- single-pass decoupled-lookback scan of (deg-1); also computes dinv, cur ----
__global__ void k_scan(int N) {
    __shared__ int s[1024];
    __shared__ int sh_vbid, sh_run;
    int tid = threadIdx.x;
    if (tid == 0) sh_vbid = atomicAdd(&g_ticket, 1);
    __syncthreads();
    int vbid = sh_vbid;
    int i = vbid * 1024 + tid;

    int v = 0;
    if (i < N) {
        int d = g_deg[i];
        g_dinv[i] = rsqrtf((float)d);
        v = d - 1;
    }
    s[tid] = v;
    __syncthreads();
    for (int off = 1; off < 1024; off <<= 1) {
        int t = (tid >= off) ? s[tid - off] : 0;
        __syncthreads();
        s[tid] += t;
        __syncthreads();
    }
    int total = s[1023];
    int ex = s[tid] - v;

    if (tid == 0) {
        if (vbid == 0) {
            atomicExch(&g_scanstat[0], (total << 2) | 2);
            sh_run = 0;
        } else {
            atomicExch(&g_scanstat[vbid], (total << 2) | 1);
            int run = 0, p = vbid - 1;
            while (true) {
                int st = atomicAdd(&g_scanstat[p], 0);
                int f = st & 3;
                if (f == 2) { run += st >> 2; break; }
                if (f == 1) { run += st >> 2; p--; }
            }
            atomicExch(&g_scanstat[vbid], ((run + total) << 2) | 2);
            sh_run = run;
        }
    }
    __syncthreads();
    if (i < N) {
        int p = sh_run + ex;
        g_ptr[i] = p;
        g_cur[i] = p;
    }
}

__global__ void k_place(const void* __restrict__ ei, int E, int N) {
    int e = blockIdx.x * blockDim.x + threadIdx.x;
    if (e >= E) return;
    int u = get_idx(ei, e);
    int v = get_idx(ei, E + e);
    if ((unsigned)u >= (unsigned)N || (unsigned)v >= (unsigned)N) return;
    int wi = __float_as_int(g_dinv[u] * g_dinv[v]);
    int p = atomicAdd(&g_cur[v], 1);
    if ((unsigned)p < 2u * EMAX) g_srcw[p] = make_int2(u, wi);
    int q = atomicAdd(&g_cur[u], 1);
    if ((unsigned)q < 2u * EMAX) g_srcw[q] = make_int2(v, wi);
}

// ---- aggregation: a[v] = dinv[v]^2*b[v] + sum_u w*b[u]; bf16 in, fp32 acc ----
// 8 lanes/node; edge records loaded by all lanes (broadcast, L1-hot); MLP=4.
__device__ __forceinline__ void acc_row(float* acc, float4 hv, float w) {
    __nv_bfloat162* hb = (__nv_bfloat162*)&hv;
    #pragma unroll
    for (int i = 0; i < 4; i++) {
        float2 f = __bfloat1622float2(hb[i]);
        acc[2*i]   += w * f.x;
        acc[2*i+1] += w * f.y;
    }
}

__global__ void k_gather(int N) {
    const __nv_bfloat16* __restrict__ in = g_b;
    int node = blockIdx.x * 32 + (threadIdx.x >> 3);
    int lane = threadIdx.x & 7;
    if (node >= N) return;

    float di = g_dinv[node];
    float sw = di * di;

    float acc[8];
    {
        float4 rv = ((const float4*)(in + (size_t)node * D))[lane];
        __nv_bfloat162* b = (__nv_bfloat162*)&rv;
        #pragma unroll
        for (int i = 0; i < 4; i++) {
            float2 f = __bfloat1622float2(b[i]);
            acc[2*i]   = sw * f.x;
            acc[2*i+1] = sw * f.y;
        }
    }

    int s0  = g_ptr[node];
    int cnt = g_deg[node] - 1;

    int t = 0;
    for (; t + 4 <= cnt; t += 4) {
        int2 e0 = g_srcw[s0 + t + 0];
        int2 e1 = g_srcw[s0 + t + 1];
        int2 e2 = g_srcw[s0 + t + 2];
        int2 e3 = g_srcw[s0 + t + 3];
        float4 h0 = ((const float4*)(in + (size_t)e0.x * D))[lane];
        float4 h1 = ((const float4*)(in + (size_t)e1.x * D))[lane];
        float4 h2 = ((const float4*)(in + (size_t)e2.x * D))[lane];
        float4 h3 = ((const float4*)(in + (size_t)e3.x * D))[lane];
        acc_row(acc, h0, __int_as_float(e0.y));
        acc_row(acc, h1, __int_as_float(e1.y));
        acc_row(acc, h2, __int_as_float(e2.y));
        acc_row(acc, h3, __int_as_float(e3.y));
    }
    for (; t < cnt; t++) {
        int2 e = g_srcw[s0 + t];
        float4 h = ((const float4*)(in + (size_t)e.x * D))[lane];
        acc_row(acc, h, __int_as_float(e.y));
    }

    float4* o = (float4*)(g_a + (size_t)node * D + lane * 8);
    o[0] = make_float4(acc[0], acc[1], acc[2], acc[3]);
    o[1] = make_float4(acc[4], acc[5], acc[6], acc[7]);
}

// ---- GEMM 1 (f32x2): x1 = leaky(a W1^T + b1); out += x1; g_b = bf16(x1) ----
__global__ void k_gemm1(const float* __restrict__ W, const float* __restrict__ b,
                        float* __restrict__ out, int N) {
    __shared__ __align__(16) float s_in[64 * 64];
    __shared__ __align__(16) float s_wt[64 * 64];  // s_wt[k*64+j] = W[j*64+k]

    int tid  = threadIdx.x;
    int base = blockIdx.x * 64;

    const float4* in4  = (const float4*)(g_a + (size_t)base * D);
    float4*       sin4 = (float4*)s_in;
    #pragma unroll
    for (int r = 0; r < 4; r++) {
        int idx4 = tid + 256 * r;
        int row  = idx4 >> 4;
        sin4[idx4] = (base + row < N) ? in4[idx4] : make_float4(0.f,0.f,0.f,0.f);
    }
    #pragma unroll
    for (int r = 0; r < 16; r++) {
        int idx = tid + 256 * r;
        s_wt[(idx >> 6) * 64 + (idx & 63)] = W[(idx & 63) * 64 + (idx >> 6)];
    }
    __syncthreads();

    int ng = tid >> 4, cg = tid & 15;
    int r0 = ng * 4;
    u64 acc[4][2] = {{0,0},{0,0},{0,0},{0,0}};   // bit pattern of (0.f,0.f)
    const ulonglong2* wt2 = (const ulonglong2*)s_wt;
    #pragma unroll
    for (int k = 0; k < 64; k++) {
        ulonglong2 wv = wt2[k * 16 + cg];        // 4 packed W cols
        #pragma unroll
        for (int r = 0; r < 4; r++) {
            float x = s_in[(r0 + r) * 64 + k];
            u64 xx = pk2(x, x);
            acc[r][0] = fma2(xx, wv.x, acc[r][0]);
            acc[r][1] = fma2(xx, wv.y, acc[r][1]);
        }
    }

    float4 bb = ((const float4*)b)[cg];
    #pragma unroll
    for (int r = 0; r < 4; r++) {
        int row = base + r0 + r;
        if (row >= N) break;
        float2 c01 = up2(acc[r][0]);
        float2 c23 = up2(acc[r][1]);
        float4 v = make_float4(c01.x + bb.x, c01.y + bb.y, c23.x + bb.z, c23.y + bb.w);
        v.x = v.x > 0.f ? v.x : 0.01f*v.x; v.y = v.y > 0.f ? v.y : 0.01f*v.y;
        v.z = v.z > 0.f ? v.z : 0.01f*v.z; v.w = v.w > 0.f ? v.w : 0.01f*v.w;
        __nv_bfloat162* bo = (__nv_bfloat162*)(g_b + (size_t)row * D + cg * 4);
        bo[0] = __floats2bfloat162_rn(v.x, v.y);
        bo[1] = __floats2bfloat162_rn(v.z, v.w);
        size_t o = (size_t)row * 16 + cg;
        float4 ov = ((const float4*)out)[o];     // holds x
        ov.x += v.x; ov.y += v.y; ov.z += v.z; ov.w += v.w;
        ((float4*)out)[o] = ov;
    }
}

// ---- GEMM 2+3 fused (f32x2): out += leaky(a W2^T + b2) + (a W3^T + b3) ----
__global__ void k_gemm23(const float* __restrict__ W2, const float* __restrict__ b2,
                         const float* __restrict__ W3, const float* __restrict__ b3,
                         float* __restrict__ out, int N) {
    __shared__ __align__(16) float s_in[64 * 64];
    __shared__ __align__(16) float s_w2[64 * 64];
    __shared__ __align__(16) float s_w3[64 * 64];

    int tid  = threadIdx.x;
    int base = blockIdx.x * 64;

    const float4* in4  = (const float4*)(g_a + (size_t)base * D);
    float4*       sin4 = (float4*)s_in;
    #pragma unroll
    for (int r = 0; r < 4; r++) {
        int idx4 = tid + 256 * r;
        int row  = idx4 >> 4;
        sin4[idx4] = (base + row < N) ? in4[idx4] : make_float4(0.f,0.f,0.f,0.f);
    }
    #pragma unroll
    for (int r = 0; r < 16; r++) {
        int idx = tid + 256 * r;
        int j = idx & 63, k = idx >> 6;
        s_w2[k * 64 + j] = W2[j * 64 + k];
        s_w3[k * 64 + j] = W3[j * 64 + k];
    }
    __syncthreads();

    int ng = tid >> 4, cg = tid & 15;
    int r0 = ng * 4;
    u64 p[4][2] = {{0,0},{0,0},{0,0},{0,0}};
    u64 q[4][2] = {{0,0},{0,0},{0,0},{0,0}};
    const ulonglong2* w22 = (const ulonglong2*)s_w2;
    const ulonglong2* w32 = (const ulonglong2*)s_w3;
    #pragma unroll
    for (int k = 0; k < 64; k++) {
        ulonglong2 u2 = w22[k * 16 + cg];
        ulonglong2 v2 = w32[k * 16 + cg];
        #pragma unroll
        for (int r = 0; r < 4; r++) {
            float x = s_in[(r0 + r) * 64 + k];
            u64 xx = pk2(x, x);
            p[r][0] = fma2(xx, u2.x, p[r][0]);
            p[r][1] = fma2(xx, u2.y, p[r][1]);
            q[r][0] = fma2(xx, v2.x, q[r][0]);
            q[r][1] = fma2(xx, v2.y, q[r][1]);
        }
    }

    float4 bb2 = ((const float4*)b2)[cg];
    float4 bb3 = ((const float4*)b3)[cg];
    #pragma unroll
    for (int r = 0; r < 4; r++) {
        int row = base + r0 + r;
        if (row >= N) break;
        float2 p01 = up2(p[r][0]), p23 = up2(p[r][1]);
        float2 q01 = up2(q[r][0]), q23 = up2(q[r][1]);
        float4 pv = make_float4(p01.x + bb2.x, p01.y + bb2.y, p23.x + bb2.z, p23.y + bb2.w);
        pv.x = pv.x > 0.f ? pv.x : 0.01f*pv.x; pv.y = pv.y > 0.f ? pv.y : 0.01f*pv.y;
        pv.z = pv.z > 0.f ? pv.z : 0.01f*pv.z; pv.w = pv.w > 0.f ? pv.w : 0.01f*pv.w;
        float4 qv = make_float4(q01.x + bb3.x, q01.y + bb3.y, q23.x + bb3.z, q23.y + bb3.w);
        size_t o = (size_t)row * 16 + cg;
        float4 ov = ((const float4*)out)[o];     // holds x + x1
        ov.x += pv.x + qv.x;
        ov.y += pv.y + qv.y;
        ov.z += pv.z + qv.z;
        ov.w += pv.w + qv.w;
        ((float4*)out)[o] = ov;
    }
}

// ---------------- launch ----------------
extern "C" void kernel_launch(void* const* d_in, const int* in_sizes, int n_in,
                              void* d_out, int out_size) {
    const void*  ei  = d_in[0];
    const float* emb = (const float*)d_in[1];
    const float* W1 = (const float*)d_in[2];
    const float* b1 = (const float*)d_in[3];
    const float* W2 = (const float*)d_in[4];
    const float* b2 = (const float*)d_in[5];
    const float* W3 = (const float*)d_in[6];
    const float* b3 = (const float*)d_in[7];
    float* out = (float*)d_out;

    int E = in_sizes[0] / 2;
    int N = in_sizes[1] / D;

    int prepb = (N * 32 + 255) / 256;             // warp per node for normalize
    k_prep <<<prepb, 256>>>(emb, (const int*)ei, out, N);
    k_count<<<(2 * E + 255) / 256, 256>>>(ei, 2 * E, N);
    int B = (N + 1023) / 1024;
    k_scan <<<B, 1024>>>(N);
    k_place<<<(E + 255) / 256, 256>>>(ei, E, N);

    int gb = (N + 63) / 64;   // gemm blocks
    int hb = (N + 31) / 32;   // gather blocks

    k_gather<<<hb, 256>>>(N);
    k_gemm1 <<<gb, 256>>>(W1, b1, out, N);
    k_gather<<<hb, 256>>>(N);
    k_gemm23<<<gb, 256>>>(W2, b2, W3, b3, out, N);
}

// round 9
// speedup vs baseline: 1.5276x; 1.0631x over previous
#include <cuda_runtime.h>
#include <cuda_bf16.h>
#include <stdint.h>

#define NMAX 100000
#define EMAX 1000000
#define D 64
#define NSCANMAX 128   // >= ceil(NMAX/1024)

typedef unsigned long long u64;

// ---------------- scratch (device globals; ~48 MB total) ----------------
__device__ __align__(16) float         g_a[NMAX * D];  // aggregation output (fp32)
__device__ __align__(16) __nv_bfloat16 g_b[NMAX * D];  // bf16 y = dinv*x, then dinv*x1
__device__ float g_dinv[NMAX];
__device__ int   g_deg [NMAX];
__device__ int   g_ptr [NMAX];
__device__ int   g_cur [NMAX];
__device__ int   g_src [2 * EMAX];    // CSR: src node only (weights folded into y)
__device__ int   g_scanstat[NSCANMAX];
__device__ int   g_ticket;
// Static init = 1 (int64 assumed). Only ever cleared (idempotent across replays).
__device__ int   g_is64 = 1;

// ---------------- f32x2 packed-FMA helpers ----------------
__device__ __forceinline__ u64 pk2(float a, float b) {
    u64 r; asm("mov.b64 %0, {%1, %2};" : "=l"(r) : "f"(a), "f"(b)); return r;
}
__device__ __forceinline__ u64 fma2(u64 a, u64 b, u64 c) {
    u64 d; asm("fma.rn.f32x2 %0, %1, %2, %3;" : "=l"(d) : "l"(a), "l"(b), "l"(c)); return d;
}
__device__ __forceinline__ float2 up2(u64 a) {
    float2 f; asm("mov.b64 {%0, %1}, %2;" : "=f"(f.x), "=f"(f.y) : "l"(a)); return f;
}

__device__ __forceinline__ int get_idx(const void* ei, int i) {
    if (g_is64) return (int)((const long long*)ei)[i];
    return ((const int*)ei)[i];
}

// ---- prep: L2-normalize x -> out (fp32) + deg init + dtype detect + scan reset ----
__global__ void k_prep(const float* __restrict__ emb, const int* __restrict__ w32,
                       float* __restrict__ out, int N) {
    int gtid = blockIdx.x * blockDim.x + threadIdx.x;
    int warp = gtid >> 5, lane = gtid & 31;
    if (warp < N) {
        float2 v = ((const float2*)(emb + (size_t)warp * D))[lane];
        float s = v.x * v.x + v.y * v.y;
        #pragma unroll
        for (int o = 16; o; o >>= 1) s += __shfl_xor_sync(0xFFFFFFFFu, s, o);
        float inv = 1.0f / fmaxf(sqrtf(s), 1e-12f);
        ((float2*)(out + (size_t)warp * D))[lane] = make_float2(v.x * inv, v.y * inv);
    }
    if (gtid < N) g_deg[gtid] = 1;                       // self loop
    if (gtid < 4096 && w32[2 * gtid + 1] != 0) g_is64 = 0;
    if (gtid < NSCANMAX) g_scanstat[gtid] = 0;
    if (gtid == 0) g_ticket = 0;
}

__global__ void k_count(const void* __restrict__ ei, int twoE, int N) {
    int i = blockIdx.x * blockDim.x + threadIdx.x;
    if (i < twoE) {
        int u = get_idx(ei, i);
        if ((unsigned)u < (unsigned)N) atomicAdd(&g_deg[u], 1);
    }
}

// ---- single-pass decoupled-lookback scan of (deg-1); also computes dinv, cur ----
__global__ void k_scan(int N) {
    __shared__ int s[1024];
    __shared__ int sh_vbid, sh_run;
    int tid = threadIdx.x;
    if (tid == 0) sh_vbid = atomicAdd(&g_ticket, 1);
    __syncthreads();
    int vbid = sh_vbid;
    int i = vbid * 1024 + tid;

    int v = 0;
    if (i < N) {
        int d = g_deg[i];
        g_dinv[i] = rsqrtf((float)d);
        v = d - 1;
    }
    s[tid] = v;
    __syncthreads();
    for (int off = 1; off < 1024; off <<= 1) {
        int t = (tid >= off) ? s[tid - off] : 0;
        __syncthreads();
        s[tid] += t;
        __syncthreads();
    }
    int total = s[1023];
    int ex = s[tid] - v;

    if (tid == 0) {
        if (vbid == 0) {
            atomicExch(&g_scanstat[0], (total << 2) | 2);
            sh_run = 0;
        } else {
            atomicExch(&g_scanstat[vbid], (total << 2) | 1);
            int run = 0, p = vbid - 1;
            while (true) {
                int st = atomicAdd(&g_scanstat[p], 0);
                int f = st & 3;
                if (f == 2) { run += st >> 2; break; }
                if (f == 1) { run += st >> 2; p--; }
            }
            atomicExch(&g_scanstat[vbid], ((run + total) << 2) | 2);
            sh_run = run;
        }
    }
    __syncthreads();
    if (i < N) {
        int p = sh_run + ex;
        g_ptr[i] = p;
        g_cur[i] = p;
    }
}

// ---- fused: blocks [0,SB) scale y=bf16(dinv*x) -> g_b ; blocks [SB,..) place edges ----
__global__ void k_place(const void* __restrict__ ei, const float* __restrict__ x,
                        int E, int N, int SB) {
    int b = blockIdx.x;
    if (b < SB) {
        // scaling: 8 lanes per row, 32 rows per block
        int row  = b * 32 + (threadIdx.x >> 3);
        int lane = threadIdx.x & 7;
        if (row >= N) return;
        float di = g_dinv[row];
        const float4* xr = (const float4*)(x + (size_t)row * D + lane * 8);
        float4 v0 = xr[0], v1 = xr[1];
        __nv_bfloat162 o0 = __floats2bfloat162_rn(di * v0.x, di * v0.y);
        __nv_bfloat162 o1 = __floats2bfloat162_rn(di * v0.z, di * v0.w);
        __nv_bfloat162 o2 = __floats2bfloat162_rn(di * v1.x, di * v1.y);
        __nv_bfloat162 o3 = __floats2bfloat162_rn(di * v1.z, di * v1.w);
        *(uint4*)(g_b + (size_t)row * D + lane * 8) =
            make_uint4(*(unsigned*)&o0, *(unsigned*)&o1, *(unsigned*)&o2, *(unsigned*)&o3);
    } else {
        int e = (b - SB) * 256 + threadIdx.x;
        if (e >= E) return;
        int u = get_idx(ei, e);
        int v = get_idx(ei, E + e);
        if ((unsigned)u >= (unsigned)N || (unsigned)v >= (unsigned)N) return;
        int p = atomicAdd(&g_cur[v], 1);
        if ((unsigned)p < 2u * EMAX) g_src[p] = u;
        int q = atomicAdd(&g_cur[u], 1);
        if ((unsigned)q < 2u * EMAX) g_src[q] = v;
    }
}

// ---- aggregation: a[v] = dinv[v] * ( y[v] + sum_u y[u] ); bf16 in, fp32 acc ----
// 8 lanes/node; 8 edges per iteration (MLP=8); unweighted sum.
__device__ __forceinline__ void acc_row(float* acc, float4 hv) {
    __nv_bfloat162* hb = (__nv_bfloat162*)&hv;
    #pragma unroll
    for (int i = 0; i < 4; i++) {
        float2 f = __bfloat1622float2(hb[i]);
        acc[2*i]   += f.x;
        acc[2*i+1] += f.y;
    }
}

__global__ void k_gather(int N) {
    const __nv_bfloat16* __restrict__ in = g_b;
    int node = blockIdx.x * 32 + (threadIdx.x >> 3);
    int lane = threadIdx.x & 7;
    if (node >= N) return;

    float acc[8];
    {
        float4 rv = ((const float4*)(in + (size_t)node * D))[lane];   // y[v]
        __nv_bfloat162* b = (__nv_bfloat162*)&rv;
        #pragma unroll
        for (int i = 0; i < 4; i++) {
            float2 f = __bfloat1622float2(b[i]);
            acc[2*i]   = f.x;
            acc[2*i+1] = f.y;
        }
    }

    int s0  = g_ptr[node];
    int cnt = g_deg[node] - 1;

    int t = 0;
    for (; t + 8 <= cnt; t += 8) {
        int s[8];
        #pragma unroll
        for (int j = 0; j < 8; j++) s[j] = g_src[s0 + t + j];
        float4 h[8];
        #pragma unroll
        for (int j = 0; j < 8; j++)
            h[j] = ((const float4*)(in + (size_t)s[j] * D))[lane];
        #pragma unroll
        for (int j = 0; j < 8; j++) acc_row(acc, h[j]);
    }
    for (; t < cnt; t++) {
        int ss = g_src[s0 + t];
        float4 h = ((const float4*)(in + (size_t)ss * D))[lane];
        acc_row(acc, h);
    }

    float di = g_dinv[node];
    float4* o = (float4*)(g_a + (size_t)node * D + lane * 8);
    o[0] = make_float4(di*acc[0], di*acc[1], di*acc[2], di*acc[3]);
    o[1] = make_float4(di*acc[4], di*acc[5], di*acc[6], di*acc[7]);
}

// ---- GEMM 1 (f32x2): x1 = leaky(a W1^T + b1); out += x1; g_b = bf16(dinv*x1) ----
__global__ void k_gemm1(const float* __restrict__ W, const float* __restrict__ b,
                        float* __restrict__ out, int N) {
    __shared__ __align__(16) float s_in[64 * 64];
    __shared__ __align__(16) float s_wt[64 * 64];  // s_wt[k*64+j] = W[j*64+k]

    int tid  = threadIdx.x;
    int base = blockIdx.x * 64;

    const float4* in4  = (const float4*)(g_a + (size_t)base * D);
    float4*       sin4 = (float4*)s_in;
    #pragma unroll
    for (int r = 0; r < 4; r++) {
        int idx4 = tid + 256 * r;
        int row  = idx4 >> 4;
        sin4[idx4] = (base + row < N) ? in4[idx4] : make_float4(0.f,0.f,0.f,0.f);
    }
    #pragma unroll
    for (int r = 0; r < 16; r++) {
        int idx = tid + 256 * r;
        s_wt[(idx >> 6) * 64 + (idx & 63)] = W[(idx & 63) * 64 + (idx >> 6)];
    }
    __syncthreads();

    int ng = tid >> 4, cg = tid & 15;
    int r0 = ng * 4;
    u64 acc[4][2] = {{0,0},{0,0},{0,0},{0,0}};
    const ulonglong2* wt2 = (const ulonglong2*)s_wt;
    #pragma unroll
    for (int k = 0; k < 64; k++) {
        ulonglong2 wv = wt2[k * 16 + cg];
        #pragma unroll
        for (int r = 0; r < 4; r++) {
            float x = s_in[(r0 + r) * 64 + k];
            u64 xx = pk2(x, x);
            acc[r][0] = fma2(xx, wv.x, acc[r][0]);
            acc[r][1] = fma2(xx, wv.y, acc[r][1]);
        }
    }

    float4 bb = ((const float4*)b)[cg];
    #pragma unroll
    for (int r = 0; r < 4; r++) {
        int row = base + r0 + r;
        if (row >= N) break;
        float2 c01 = up2(acc[r][0]);
        float2 c23 = up2(acc[r][1]);
        float4 v = make_float4(c01.x + bb.x, c01.y + bb.y, c23.x + bb.z, c23.y + bb.w);
        v.x = v.x > 0.f ? v.x : 0.01f*v.x; v.y = v.y > 0.f ? v.y : 0.01f*v.y;
        v.z = v.z > 0.f ? v.z : 0.01f*v.z; v.w = v.w > 0.f ? v.w : 0.01f*v.w;
        float di = g_dinv[row];
        __nv_bfloat162* bo = (__nv_bfloat162*)(g_b + (size_t)row * D + cg * 4);
        bo[0] = __floats2bfloat162_rn(di * v.x, di * v.y);
        bo[1] = __floats2bfloat162_rn(di * v.z, di * v.w);
        size_t o = (size_t)row * 16 + cg;
        float4 ov = ((const float4*)out)[o];     // holds x
        ov.x += v.x; ov.y += v.y; ov.z += v.z; ov.w += v.w;
        ((float4*)out)[o] = ov;
    }
}

// ---- GEMM 2+3 fused (f32x2): out += leaky(a W2^T + b2) + (a W3^T + b3) ----
__global__ void k_gemm23(const float* __restrict__ W2, const float* __restrict__ b2,
                         const float* __restrict__ W3, const float* __restrict__ b3,
                         float* __restrict__ out, int N) {
    __shared__ __align__(16) float s_in[64 * 64];
    __shared__ __align__(16) float s_w2[64 * 64];
    __shared__ __align__(16) float s_w3[64 * 64];

    int tid  = threadIdx.x;
    int base = blockIdx.x * 64;

    const float4* in4  = (const float4*)(g_a + (size_t)base * D);
    float4*       sin4 = (float4*)s_in;
    #pragma unroll
    for (int r = 0; r < 4; r++) {
        int idx4 = tid + 256 * r;
        int row  = idx4 >> 4;
        sin4[idx4] = (base + row < N) ? in4[idx4] : make_float4(0.f,0.f,0.f,0.f);
    }
    #pragma unroll
    for (int r = 0; r < 16; r++) {
        int idx = tid + 256 * r;
        int j = idx & 63, k = idx >> 6;
        s_w2[k * 64 + j] = W2[j * 64 + k];
        s_w3[k * 64 + j] = W3[j * 64 + k];
    }
    __syncthreads();

    int ng = tid >> 4, cg = tid & 15;
    int r0 = ng * 4;
    u64 p[4][2] = {{0,0},{0,0},{0,0},{0,0}};
    u64 q[4][2] = {{0,0},{0,0},{0,0},{0,0}};
    const ulonglong2* w22 = (const ulonglong2*)s_w2;
    const ulonglong2* w32 = (const ulonglong2*)s_w3;
    #pragma unroll
    for (int k = 0; k < 64; k++) {
        ulonglong2 u2 = w22[k * 16 + cg];
        ulonglong2 v2 = w32[k * 16 + cg];
        #pragma unroll
        for (int r = 0; r < 4; r++) {
            float x = s_in[(r0 + r) * 64 + k];
            u64 xx = pk2(x, x);
            p[r][0] = fma2(xx, u2.x, p[r][0]);
            p[r][1] = fma2(xx, u2.y, p[r][1]);
            q[r][0] = fma2(xx, v2.x, q[r][0]);
            q[r][1] = fma2(xx, v2.y, q[r][1]);
        }
    }

    float4 bb2 = ((const float4*)b2)[cg];
    float4 bb3 = ((const float4*)b3)[cg];
    #pragma unroll
    for (int r = 0; r < 4; r++) {
        int row = base + r0 + r;
        if (row >= N) break;
        float2 p01 = up2(p[r][0]), p23 = up2(p[r][1]);
        float2 q01 = up2(q[r][0]), q23 = up2(q[r][1]);
        float4 pv = make_float4(p01.x + bb2.x, p01.y + bb2.y, p23.x + bb2.z, p23.y + bb2.w);
        pv.x = pv.x > 0.f ? pv.x : 0.01f*pv.x; pv.y = pv.y > 0.f ? pv.y : 0.01f*pv.y;
        pv.z = pv.z > 0.f ? pv.z : 0.01f*pv.z; pv.w = pv.w > 0.f ? pv.w : 0.01f*pv.w;
        float4 qv = make_float4(q01.x + bb3.x, q01.y + bb3.y, q23.x + bb3.z, q23.y + bb3.w);
        size_t o = (size_t)row * 16 + cg;
        float4 ov = ((const float4*)out)[o];     // holds x + x1
        ov.x += pv.x + qv.x;
        ov.y += pv.y + qv.y;
        ov.z += pv.z + qv.z;
        ov.w += pv.w + qv.w;
        ((float4*)out)[o] = ov;
    }
}

// ---------------- launch ----------------
extern "C" void kernel_launch(void* const* d_in, const int* in_sizes, int n_in,
                              void* d_out, int out_size) {
    const void*  ei  = d_in[0];
    const float* emb = (const float*)d_in[1];
    const float* W1 = (const float*)d_in[2];
    const float* b1 = (const float*)d_in[3];
    const float* W2 = (const float*)d_in[4];
    const float* b2 = (const float*)d_in[5];
    const float* W3 = (const float*)d_in[6];
    const float* b3 = (const float*)d_in[7];
    float* out = (float*)d_out;

    int E = in_sizes[0] / 2;
    int N = in_sizes[1] / D;

    int prepb = (N * 32 + 255) / 256;             // warp per node for normalize
    k_prep <<<prepb, 256>>>(emb, (const int*)ei, out, N);
    k_count<<<(2 * E + 255) / 256, 256>>>(ei, 2 * E, N);
    int B = (N + 1023) / 1024;
    k_scan <<<B, 1024>>>(N);
    int SB = (N + 31) / 32;                       // scale blocks
    int PB = (E + 255) / 256;                     // place blocks
    k_place<<<SB + PB, 256>>>(ei, out, E, N, SB);

    int gb = (N + 63) / 64;   // gemm blocks
    int hb = (N + 31) / 32;   // gather blocks

    k_gather<<<hb, 256>>>(N);
    k_gemm1 <<<gb, 256>>>(W1, b1, out, N);
    k_gather<<<hb, 256>>>(N);
    k_gemm23<<<gb, 256>>>(W2, b2, W3, b3, out, N);
}